// round 1
// baseline (speedup 1.0000x reference)
#include <cuda_runtime.h>
#include <cstddef>

#define HH 512
#define WW 512
#define CC 64
#define HWSZ (HH*WW)
#define KS 576
#define WQ_SIZE 36864

// ---------------- scratch (no allocations allowed) ----------------
__device__ int   g_act_i[KS];   // act_scale as float bits (nonneg -> int-monotonic)
__device__ float g_qm[KS];      // 1 / (scale_j * s_x)
__device__ float g_sx;          // s_x

// ---------------- K0: zero the atomic-max buffer ----------------
__global__ void k0_zero() {
    int i = blockIdx.x * blockDim.x + threadIdx.x;
    if (i < KS) g_act_i[i] = 0;
}

// ---------------- K1: per-(c,kh,kw) activation abs-max ----------------
// act[c,kh,kw] = max|input[c, Hrange(kh), Wrange(kw)]|
//   kh=0: rows 0..510, kh=1: all, kh=2: rows 1..511 (same for kw over cols).
// Per row we need 3 maxes: excl-last-col (kw=0), all (kw=1), excl-first-col (kw=2).
__global__ __launch_bounds__(256) void k1_actmax(const float* __restrict__ in) {
    int c    = blockIdx.x;          // 64
    int hb   = blockIdx.y;          // 64 groups of 8 rows
    int warp = threadIdx.x >> 5;    // row within group
    int lane = threadIdx.x & 31;
    int h    = hb * 8 + warp;

    const float* row = in + (size_t)c * HWSZ + (size_t)h * WW + lane * 16;
    float v[16];
#pragma unroll
    for (int i = 0; i < 4; i++) {
        float4 t = *(const float4*)(row + i * 4);
        v[i*4+0] = fabsf(t.x); v[i*4+1] = fabsf(t.y);
        v[i*4+2] = fabsf(t.z); v[i*4+3] = fabsf(t.w);
    }
    float mMid = 0.f;
#pragma unroll
    for (int i = 1; i < 15; i++) mMid = fmaxf(mMid, v[i]);
    float mExFirst = fmaxf(mMid, v[15]);   // excludes this thread's first elem
    float mExLast  = fmaxf(mMid, v[0]);    // excludes this thread's last elem
    float mAll     = fmaxf(mExFirst, v[0]);

    // core = max over pixels with 0 < w < 511 ; v0/v511 = the border pixels
    float core, v0 = 0.f, v511 = 0.f;
    if (lane == 0)       { core = mExFirst; v0 = v[0]; }
    else if (lane == 31) { core = mExLast;  v511 = v[15]; }
    else                 { core = mAll; }

#pragma unroll
    for (int o = 16; o; o >>= 1) {
        core = fmaxf(core, __shfl_xor_sync(0xffffffffu, core, o));
        v0   = fmaxf(v0,   __shfl_xor_sync(0xffffffffu, v0,   o));
        v511 = fmaxf(v511, __shfl_xor_sync(0xffffffffu, v511, o));
    }

    __shared__ float rm[8][3];
    if (lane == 0) {
        rm[warp][0] = fmaxf(core, v0);                  // kw=0: cols 0..510
        rm[warp][1] = fmaxf(fmaxf(core, v0), v511);     // kw=1: all cols
        rm[warp][2] = fmaxf(core, v511);                // kw=2: cols 1..511
    }
    __syncthreads();

    if (threadIdx.x < 9) {
        int kh = threadIdx.x / 3, kw = threadIdx.x % 3;
        float m = 0.f;
#pragma unroll
        for (int r = 0; r < 8; r++) {
            int hh = hb * 8 + r;
            bool ok = (kh == 0) ? (hh <= 510) : ((kh == 2) ? (hh >= 1) : true);
            if (ok) m = fmaxf(m, rm[r][kw]);
        }
        atomicMax(&g_act_i[c * 9 + threadIdx.x], __float_as_int(m));
    }
}

// ---------------- K2: scales + s_x + s_w + quantized weight output ----------------
__global__ __launch_bounds__(576) void k2_scales(const float* __restrict__ wgt,
                                                 float* __restrict__ out_wq) {
    int j = threadIdx.x;            // 0..575 : j = c*9 + kh*3 + kw
    __shared__ float sA[18], sW[18];
    __shared__ float sh_ax, sh_aw;

    float act = __int_as_float(g_act_i[j]);
    float wmax = 0.f;
#pragma unroll 8
    for (int co = 0; co < 64; co++)
        wmax = fmaxf(wmax, fabsf(wgt[co * KS + j]));

    float scale = sqrtf(act) / sqrtf(wmax);   // alpha = 0.5
    if (scale == 0.f) scale = 1.f;
    float candx = act / scale;                // column max of |x/scale|
    float candw = wmax * scale;               // column max of |w*scale|

#pragma unroll
    for (int o = 16; o; o >>= 1) {
        candx = fmaxf(candx, __shfl_xor_sync(0xffffffffu, candx, o));
        candw = fmaxf(candw, __shfl_xor_sync(0xffffffffu, candw, o));
    }
    if ((j & 31) == 0) { sA[j >> 5] = candx; sW[j >> 5] = candw; }
    __syncthreads();
    if (j == 0) {
        float ax = 0.f, aw = 0.f;
        for (int r = 0; r < 18; r++) { ax = fmaxf(ax, sA[r]); aw = fmaxf(aw, sW[r]); }
        sh_ax = ax; sh_aw = aw;
    }
    __syncthreads();

    float sx = (sh_ax > 0.f) ? (sh_ax / 127.0f) : 1.f;
    float sw = (sh_aw > 0.f) ? (sh_aw / 127.0f) : 1.f;

    g_qm[j] = 1.0f / (scale * sx);
    if (j == 0) g_sx = sx;

    // wq[cout, kh, kw, c] = rint(clip(w*scale/sw)) * sw
    int c  = j / 9;
    int kh = (j % 9) / 3;
    int kw = j % 3;
    float inv_sw = 1.0f / sw;
#pragma unroll 4
    for (int co = 0; co < 64; co++) {
        float wv = wgt[co * KS + j] * scale;
        float q  = rintf(fminf(fmaxf(wv * inv_sw, -127.f), 127.f));
        out_wq[((co * 3 + kh) * 3 + kw) * 64 + c] = q * sw;
    }
}

// ---------------- K3: fused quantize + fold + NCHW->NHWC ----------------
// xf[h,w,c] = s_x * sum over valid (kh,kw) of rint( input[c,h,w] * qm[c,kh,kw] )
// Tap (kh,kw) valid iff (h+1-kh) in [0,511] and (w+1-kw) in [0,511].
__global__ __launch_bounds__(256) void k3_fold(const float* __restrict__ in,
                                               float* __restrict__ out) {
    __shared__ float s_in[CC][33];     // stride 33: conflict-free both phases
    __shared__ float s_qm[KS];

    const int h   = blockIdx.y;        // 512
    const int wt  = blockIdx.x;        // 16 tiles of 32 pixels
    const int tid = threadIdx.x;

    for (int i = tid; i < KS; i += 256) s_qm[i] = g_qm[i];

    // Load 64 channels x 32 w-pixels of row h (coalesced float4 reads)
    const float* base = in + (size_t)h * WW + wt * 32;
    for (int i = tid; i < 512; i += 256) {
        int cc = i >> 3, w4 = i & 7;
        float4 t = *(const float4*)(base + (size_t)cc * HWSZ + w4 * 4);
        s_in[cc][w4 * 4 + 0] = t.x;
        s_in[cc][w4 * 4 + 1] = t.y;
        s_in[cc][w4 * 4 + 2] = t.z;
        s_in[cc][w4 * 4 + 3] = t.w;
    }
    __syncthreads();

    const float sx = g_sx;
    const int c  = tid & 63;
    const int g  = tid >> 6;           // 0..3, 8 pixels each
    const int w0 = wt * 32 + g * 8;

    float m[9];
#pragma unroll
    for (int k = 0; k < 9; k++) m[k] = s_qm[c * 9 + k];
    if (h == 0)   { m[6] = 0.f; m[7] = 0.f; m[8] = 0.f; }  // kh=2 invalid
    if (h == 511) { m[0] = 0.f; m[1] = 0.f; m[2] = 0.f; }  // kh=0 invalid

    const float MAG = 12582912.0f;     // 1.5 * 2^23 : round-half-even
    float res[8];
    const bool wedge = (w0 == 0) | (w0 + 7 == 511);   // warp-uniform

    if (!wedge) {
#pragma unroll
        for (int p = 0; p < 8; p++) {
            float v = s_in[c][g * 8 + p];
            float acc = 0.f;
#pragma unroll
            for (int k = 0; k < 9; k++) {
                float t = fmaf(v, m[k], MAG);
                acc += (t - MAG);
            }
            res[p] = acc * sx;
        }
    } else {
#pragma unroll
        for (int p = 0; p < 8; p++) {
            int w = w0 + p;
            float v = s_in[c][g * 8 + p];
            float acc = 0.f;
#pragma unroll
            for (int k = 0; k < 9; k++) {
                float mk = m[k];
                if (w == 0   && (k % 3) == 2) mk = 0.f;   // kw=2 invalid
                if (w == 511 && (k % 3) == 0) mk = 0.f;   // kw=0 invalid
                float t = fmaf(v, mk, MAG);
                acc += (t - MAG);
            }
            res[p] = acc * sx;
        }
    }

    float* o = out + ((size_t)(h * WW + w0)) * 64 + c;
#pragma unroll
    for (int p = 0; p < 8; p++) o[p * 64] = res[p];
}

// ---------------- launch ----------------
extern "C" void kernel_launch(void* const* d_in, const int* in_sizes, int n_in,
                              void* d_out, int out_size) {
    const float* inp = (const float*)d_in[0];
    const float* wgt = (const float*)d_in[1];
    if (n_in >= 2 && in_sizes[0] == WQ_SIZE) {   // defensive: swap if metadata order differs
        const float* t = inp; inp = wgt; wgt = t;
    }
    float* out_wq = (float*)d_out;
    float* out_xf = (float*)d_out + WQ_SIZE;

    k0_zero<<<1, 576>>>();
    {
        dim3 grid(64, 64);
        k1_actmax<<<grid, 256>>>(inp);
    }
    k2_scales<<<1, 576>>>(wgt, out_wq);
    {
        dim3 grid(16, 512);
        k3_fold<<<grid, 256>>>(inp, out_xf);
    }
}